// round 11
// baseline (speedup 1.0000x reference)
#include <cuda_runtime.h>
#include <cuda_fp16.h>
#include <cstdint>

// Problem constants (fixed by reference setup)
#define HSZ 8
#define WSZ 8
#define NTOK 64
#define DIM 192
#define NH 6
#define HEAD_DIM 32
#define POS_DIM 12
#define NPOS 225
#define SCALE 0.17677669529663689f   // 32^-0.5

#define PADH 40      // halves per row, Q/K/V tiles (80B rows -> LDSM conflict-free)

// smem (in halves): two head slots, each {Q,K,V: 64*PADH}
#define SLOT_H   (3 * 64 * PADH)
#define SMH_Q(s) ((s) * SLOT_H)
#define SMH_K(s) (SMH_Q(s) + 64 * PADH)
#define SMH_V(s) (SMH_K(s) + 64 * PADH)
#define SMH_TOT  (2 * SLOT_H)
#define SMEM_BYTES (SMH_TOT * 2)

// bias pre-laid-out as fp16 S-fragments: [head][m][nt][lane] -> half4 (c0..c3)
// element index = (((h*4 + m)*8 + nt)*128 + lane)  (uint2 units)
__device__ __align__(16) uint2 g_bfrag[NH * 4 * 8 * 128];

// ---------------------------------------------------------------------------
// Kernel A (fused): weights -> smem, tiny MLP -> s_pos, then expand to
// fragment-layout fp16 table g_bfrag. One launch, no gmem round-trip.
// ---------------------------------------------------------------------------
__device__ __forceinline__ void ln_relu_s(float* x, const float* g, const float* b, float* y) {
    float m = 0.f;
#pragma unroll
    for (int j = 0; j < POS_DIM; ++j) m += x[j];
    m *= (1.0f / POS_DIM);
    float v = 0.f;
#pragma unroll
    for (int j = 0; j < POS_DIM; ++j) { float d = x[j] - m; v += d * d; }
    v *= (1.0f / POS_DIM);
    float inv = rsqrtf(v + 1e-5f);
#pragma unroll
    for (int j = 0; j < POS_DIM; ++j) {
        float t = (x[j] - m) * inv * g[j] + b[j];
        y[j] = t > 0.f ? t : 0.f;
    }
}

__global__ void rpe_mlp_kernel(
    const float* __restrict__ w_proj, const float* __restrict__ b_proj,
    const float* __restrict__ ln1_g, const float* __restrict__ ln1_b,
    const float* __restrict__ w1, const float* __restrict__ b1,
    const float* __restrict__ ln2_g, const float* __restrict__ ln2_b,
    const float* __restrict__ w2, const float* __restrict__ b2,
    const float* __restrict__ ln3_g, const float* __restrict__ ln3_b,
    const float* __restrict__ w3, const float* __restrict__ b3)
{
    __shared__ float s_wp[2 * POS_DIM], s_bp[POS_DIM];
    __shared__ float s_g1[POS_DIM], s_c1[POS_DIM], s_w1[POS_DIM * POS_DIM], s_b1[POS_DIM];
    __shared__ float s_g2[POS_DIM], s_c2[POS_DIM], s_w2[POS_DIM * POS_DIM], s_b2[POS_DIM];
    __shared__ float s_g3[POS_DIM], s_c3[POS_DIM], s_w3[POS_DIM * NH], s_b3[NH];
    __shared__ float s_pos[NPOS * NH];

    const int tid = threadIdx.x;
    for (int i = tid; i < POS_DIM * POS_DIM; i += 256) { s_w1[i] = w1[i]; s_w2[i] = w2[i]; }
    if (tid < POS_DIM * NH) s_w3[tid] = w3[tid];
    if (tid < 2 * POS_DIM) s_wp[tid] = w_proj[tid];
    if (tid < POS_DIM) {
        s_bp[tid] = b_proj[tid];
        s_g1[tid] = ln1_g[tid]; s_c1[tid] = ln1_b[tid]; s_b1[tid] = b1[tid];
        s_g2[tid] = ln2_g[tid]; s_c2[tid] = ln2_b[tid]; s_b2[tid] = b2[tid];
        s_g3[tid] = ln3_g[tid]; s_c3[tid] = ln3_b[tid];
    }
    if (tid < NH) s_b3[tid] = b3[tid];
    __syncthreads();

    if (tid < NPOS) {
        const int m = tid;
        float in0 = (float)(m / (2 * WSZ - 1) - (HSZ - 1));
        float in1 = (float)(m % (2 * WSZ - 1) - (WSZ - 1));

        float x[POS_DIM], y[POS_DIM];
#pragma unroll
        for (int j = 0; j < POS_DIM; ++j)
            x[j] = in0 * s_wp[j] + in1 * s_wp[POS_DIM + j] + s_bp[j];

        ln_relu_s(x, s_g1, s_c1, y);
#pragma unroll
        for (int j = 0; j < POS_DIM; ++j) {
            float s = s_b1[j];
#pragma unroll
            for (int kk = 0; kk < POS_DIM; ++kk) s += y[kk] * s_w1[kk * POS_DIM + j];
            x[j] = s;
        }
        ln_relu_s(x, s_g2, s_c2, y);
#pragma unroll
        for (int j = 0; j < POS_DIM; ++j) {
            float s = s_b2[j];
#pragma unroll
            for (int kk = 0; kk < POS_DIM; ++kk) s += y[kk] * s_w2[kk * POS_DIM + j];
            x[j] = s;
        }
        ln_relu_s(x, s_g3, s_c3, y);
#pragma unroll
        for (int h = 0; h < NH; ++h) {
            float s = s_b3[h];
#pragma unroll
            for (int kk = 0; kk < POS_DIM; ++kk) s += y[kk] * s_w3[kk * NH + h];
            s_pos[m * NH + h] = s;
        }
    }
    __syncthreads();

    // phase 2: expand to fragment-layout fp16 table.
    // entry idx = ((h*4 + m)*8 + nt)*128 + lane ; holds half4 {c0,c1,c2,c3}
    for (int idx = tid; idx < NH * 4 * 8 * 128; idx += 256) {
        int lane = idx & 127;
        int nt   = (idx >> 7) & 7;
        int m    = (idx >> 10) & 3;
        int h    = idx >> 12;
        __half hv[4];
#pragma unroll
        for (int c = 0; c < 4; ++c) {
            int r   = m * 16 + ((lane >> 2) & 7) + ((c >> 1) ? 8 : 0);  // S row
            int col = nt * 8 + 2 * (lane & 3) + (c & 1);                // S col
            int dy = (r >> 3) - (col >> 3) + 7;
            int dx = (r & 7) - (col & 7) + 7;
            hv[c] = __float2half(s_pos[(dy * 15 + dx) * NH + h]);
        }
        union { __half h[4]; uint2 u; } pk;
        pk.h[0] = hv[0]; pk.h[1] = hv[1]; pk.h[2] = hv[2]; pk.h[3] = hv[3];
        g_bfrag[idx] = pk.u;
    }
}

// ---------------------------------------------------------------------------
// MMA / LDSM helpers
// ---------------------------------------------------------------------------
__device__ __forceinline__ uint32_t sh_addr(const void* p) {
    return (uint32_t)__cvta_generic_to_shared(p);
}
__device__ __forceinline__ void ldsm_x4(uint32_t& r0, uint32_t& r1, uint32_t& r2, uint32_t& r3, uint32_t a) {
    asm volatile("ldmatrix.sync.aligned.m8n8.x4.shared.b16 {%0,%1,%2,%3},[%4];"
                 : "=r"(r0), "=r"(r1), "=r"(r2), "=r"(r3) : "r"(a));
}
__device__ __forceinline__ void ldsm_x4_t(uint32_t& r0, uint32_t& r1, uint32_t& r2, uint32_t& r3, uint32_t a) {
    asm volatile("ldmatrix.sync.aligned.m8n8.x4.trans.shared.b16 {%0,%1,%2,%3},[%4];"
                 : "=r"(r0), "=r"(r1), "=r"(r2), "=r"(r3) : "r"(a));
}
__device__ __forceinline__ void mma_f16(float c[4], const uint32_t a[4], uint32_t b0, uint32_t b1) {
    asm volatile("mma.sync.aligned.m16n8k16.row.col.f32.f16.f16.f32 "
                 "{%0,%1,%2,%3},{%4,%5,%6,%7},{%8,%9},{%0,%1,%2,%3};"
                 : "+f"(c[0]), "+f"(c[1]), "+f"(c[2]), "+f"(c[3])
                 : "r"(a[0]), "r"(a[1]), "r"(a[2]), "r"(a[3]), "r"(b0), "r"(b1));
}
__device__ __forceinline__ void st_half8(__half* p, float4 f0, float4 f1) {
    union { __half2 h[4]; uint4 u; } t;
    t.h[0] = __floats2half2_rn(f0.x, f0.y);
    t.h[1] = __floats2half2_rn(f0.z, f0.w);
    t.h[2] = __floats2half2_rn(f1.x, f1.y);
    t.h[3] = __floats2half2_rn(f1.z, f1.w);
    *(uint4*)p = t.u;
}

// ---------------------------------------------------------------------------
// Kernel B: one CTA per 8x8 window. 3 iterations of 2 heads.
// 8 warps = 4 m-tiles x 2 heads; warp computes full 16x64 score rows.
// Bias: 8 coalesced LDG.64 of fp16 fragments -> accumulator init.
// ---------------------------------------------------------------------------
__global__ __launch_bounds__(256, 4) void attn_kernel(
    const float* __restrict__ q, const float* __restrict__ k,
    const float* __restrict__ v, float* __restrict__ out)
{
    extern __shared__ __half smh[];

    const int tid = threadIdx.x;
    const int lane = tid & 31;
    const int wid = tid >> 5;
    const int t = lane & 3;        // 0..3
    const int m = wid & 3;         // m-tile
    const int hs = wid >> 2;       // head slot (0/1)

    const int w = blockIdx.x;
    const int b = w >> 10;
    const int wy = (w >> 5) & 31;
    const int wx = w & 31;

    // staging addresses: thread handles token tid>>2, channels (tid&3)*8..+8
    const int stok = tid >> 2;
    const int sch = (tid & 3) * 8;
    const int sy = wy * HSZ + (stok >> 3);
    const int sx = wx * WSZ + (stok & 7);
    const int gtok = ((b * 256 + sy) * 256 + sx) * DIM + sch;
    const int soff = stok * PADH + sch;

    // this warp's output rows
    const int r0 = m * 16 + (lane >> 2);
    const int y0 = r0 >> 3, x0 = r0 & 7;   // r1 = r0+8: one image row below
    const int obase0 = ((b * 256 + wy * HSZ + y0) * 256 + wx * WSZ + x0) * DIM;
    const int obase1 = obase0 + 256 * DIM;

    // bias fragment base for this (m, lane); head offset added per iteration
    const uint2* bfrag_m = &g_bfrag[(m * 8) * 128 + lane];

    // LDSM lane addressing
    const int a_row = m * 16 + (lane & 7) + ((lane >> 3) & 1) * 8;
    const int a_colp = (lane >> 4) * 8;
    const int bk_row = lane & 7;
    const int bk_col = (lane >> 3) * 8;
    const int bv_tok = (lane >> 3) * 8 + (lane & 7);

#pragma unroll 1
    for (int it = 0; it < 3; ++it) {
        const int h0 = it * 2;

        // ---- stage 2 heads: Q(scaled),K,V as fp16 ----
#pragma unroll
        for (int s = 0; s < 2; ++s) {
            const int go = gtok + (h0 + s) * HEAD_DIM;
            float4 f0, f1;
            f0 = *(const float4*)(q + go);
            f1 = *(const float4*)(q + go + 4);
            f0.x *= SCALE; f0.y *= SCALE; f0.z *= SCALE; f0.w *= SCALE;
            f1.x *= SCALE; f1.y *= SCALE; f1.z *= SCALE; f1.w *= SCALE;
            st_half8(&smh[SMH_Q(s) + soff], f0, f1);
            f0 = *(const float4*)(k + go);
            f1 = *(const float4*)(k + go + 4);
            st_half8(&smh[SMH_K(s) + soff], f0, f1);
            f0 = *(const float4*)(v + go);
            f1 = *(const float4*)(v + go + 4);
            st_half8(&smh[SMH_V(s) + soff], f0, f1);
        }
        __syncthreads();

        const __half* sQ = &smh[SMH_Q(hs)];
        const __half* sK = &smh[SMH_K(hs)];
        const __half* sV = &smh[SMH_V(hs)];
        const int head = h0 + hs;

        // ---- S accumulators initialized from fp16 bias fragments ----
        // 8 coalesced LDG.64 (256B per warp each), 16 transient regs.
        float sc[8][4];
        {
            const uint2* bf = bfrag_m + head * (4 * 8 * 128);
#pragma unroll
            for (int nt = 0; nt < 8; ++nt) {
                uint2 bv = bf[nt * 128];
                union { uint32_t u; __half2 h; } lo, hi;
                lo.u = bv.x; hi.u = bv.y;
                float2 f01 = __half22float2(lo.h);
                float2 f23 = __half22float2(hi.h);
                sc[nt][0] = f01.x; sc[nt][1] = f01.y;
                sc[nt][2] = f23.x; sc[nt][3] = f23.y;
            }
        }

        // ---- S += Q K^T : 16x64 per warp ----
        uint32_t aq[2][4];
#pragma unroll
        for (int kt = 0; kt < 2; ++kt)
            ldsm_x4(aq[kt][0], aq[kt][1], aq[kt][2], aq[kt][3],
                    sh_addr(&sQ[a_row * PADH + kt * 16 + a_colp]));

#pragma unroll
        for (int nt = 0; nt < 8; ++nt) {
            uint32_t b0, b1, b2, b3;
            ldsm_x4(b0, b1, b2, b3, sh_addr(&sK[(nt * 8 + bk_row) * PADH + bk_col]));
            mma_f16(sc[nt], aq[0], b0, b1);
            mma_f16(sc[nt], aq[1], b2, b3);
        }

        // ---- warp-local softmax (rows r0, r1) ----
        float mx0 = -1e30f, mx1 = -1e30f;
#pragma unroll
        for (int nt = 0; nt < 8; ++nt) {
            mx0 = fmaxf(mx0, fmaxf(sc[nt][0], sc[nt][1]));
            mx1 = fmaxf(mx1, fmaxf(sc[nt][2], sc[nt][3]));
        }
        mx0 = fmaxf(mx0, __shfl_xor_sync(0xffffffffu, mx0, 1));
        mx0 = fmaxf(mx0, __shfl_xor_sync(0xffffffffu, mx0, 2));
        mx1 = fmaxf(mx1, __shfl_xor_sync(0xffffffffu, mx1, 1));
        mx1 = fmaxf(mx1, __shfl_xor_sync(0xffffffffu, mx1, 2));

        float s0 = 0.f, s1 = 0.f;
#pragma unroll
        for (int nt = 0; nt < 8; ++nt) {
            sc[nt][0] = __expf(sc[nt][0] - mx0);
            sc[nt][1] = __expf(sc[nt][1] - mx0);
            sc[nt][2] = __expf(sc[nt][2] - mx1);
            sc[nt][3] = __expf(sc[nt][3] - mx1);
            s0 += sc[nt][0] + sc[nt][1];
            s1 += sc[nt][2] + sc[nt][3];
        }
        s0 += __shfl_xor_sync(0xffffffffu, s0, 1);
        s0 += __shfl_xor_sync(0xffffffffu, s0, 2);
        s1 += __shfl_xor_sync(0xffffffffu, s1, 1);
        s1 += __shfl_xor_sync(0xffffffffu, s1, 2);
        const float inv0 = __frcp_rn(s0);
        const float inv1 = __frcp_rn(s1);

        // ---- pack P directly into A fragments (no smem round-trip) ----
        uint32_t pa[4][4];
#pragma unroll
        for (int kt = 0; kt < 4; ++kt) {
            union { __half2 h; uint32_t u; } u0, u1, u2, u3;
            u0.h = __floats2half2_rn(sc[2 * kt][0] * inv0, sc[2 * kt][1] * inv0);
            u1.h = __floats2half2_rn(sc[2 * kt][2] * inv1, sc[2 * kt][3] * inv1);
            u2.h = __floats2half2_rn(sc[2 * kt + 1][0] * inv0, sc[2 * kt + 1][1] * inv0);
            u3.h = __floats2half2_rn(sc[2 * kt + 1][2] * inv1, sc[2 * kt + 1][3] * inv1);
            pa[kt][0] = u0.u; pa[kt][1] = u1.u; pa[kt][2] = u2.u; pa[kt][3] = u3.u;
        }

        // ---- O = P V : 16x32 per warp; per-nt accumulators (low reg pressure) ----
        const int ocol = head * HEAD_DIM + 2 * t;
#pragma unroll
        for (int nt = 0; nt < 4; ++nt) {
            float oc[4] = {0.f, 0.f, 0.f, 0.f};
#pragma unroll
            for (int hh = 0; hh < 2; ++hh) {
                uint32_t b0, b1, b2, b3;
                ldsm_x4_t(b0, b1, b2, b3,
                          sh_addr(&sV[(hh * 32 + bv_tok) * PADH + nt * 8]));
                mma_f16(oc, pa[2 * hh], b0, b1);
                mma_f16(oc, pa[2 * hh + 1], b2, b3);
            }
            *(float2*)&out[obase0 + ocol + nt * 8] = make_float2(oc[0], oc[1]);
            *(float2*)&out[obase1 + ocol + nt * 8] = make_float2(oc[2], oc[3]);
        }
        __syncthreads();   // protect smem before next iteration's stage
    }
}

// ---------------------------------------------------------------------------
extern "C" void kernel_launch(void* const* d_in, const int* in_sizes, int n_in,
                              void* d_out, int out_size)
{
    const float* q = (const float*)d_in[0];
    const float* k = (const float*)d_in[1];
    const float* v = (const float*)d_in[2];
    // d_in[3] = H, d_in[4] = W (int32, fixed 256)
    const float* w_proj = (const float*)d_in[5];
    const float* b_proj = (const float*)d_in[6];
    const float* ln1_g  = (const float*)d_in[7];
    const float* ln1_b  = (const float*)d_in[8];
    const float* w1     = (const float*)d_in[9];
    const float* b1     = (const float*)d_in[10];
    const float* ln2_g  = (const float*)d_in[11];
    const float* ln2_b  = (const float*)d_in[12];
    const float* w2     = (const float*)d_in[13];
    const float* b2     = (const float*)d_in[14];
    const float* ln3_g  = (const float*)d_in[15];
    const float* ln3_b  = (const float*)d_in[16];
    const float* w3     = (const float*)d_in[17];
    const float* b3     = (const float*)d_in[18];

    int B = in_sizes[0] / (256 * 256 * DIM);

    cudaFuncSetAttribute(attn_kernel, cudaFuncAttributeMaxDynamicSharedMemorySize, SMEM_BYTES);

    rpe_mlp_kernel<<<1, 256>>>(w_proj, b_proj, ln1_g, ln1_b, w1, b1,
                               ln2_g, ln2_b, w2, b2, ln3_g, ln3_b, w3, b3);
    attn_kernel<<<B * 1024, 256, SMEM_BYTES>>>(q, k, v, (float*)d_out);
}

// round 12
// speedup vs baseline: 1.0373x; 1.0373x over previous
#include <cuda_runtime.h>
#include <cuda_fp16.h>
#include <cstdint>

// Problem constants (fixed by reference setup)
#define HSZ 8
#define WSZ 8
#define NTOK 64
#define DIM 192
#define NH 6
#define HEAD_DIM 32
#define POS_DIM 12
#define NPOS 225
#define SCALE 0.17677669529663689f   // 32^-0.5

#define PADH 40      // halves per row, Q/K/V tiles (80B rows -> LDSM conflict-free)

// smem (in halves): two head slots, each {Q,K,V: 64*PADH}
#define SLOT_H   (3 * 64 * PADH)
#define SMH_Q(s) ((s) * SLOT_H)
#define SMH_K(s) (SMH_Q(s) + 64 * PADH)
#define SMH_V(s) (SMH_K(s) + 64 * PADH)
#define SMH_TOT  (2 * SLOT_H)
#define SMEM_BYTES (SMH_TOT * 2)

// bias as fp16 S-fragments, COMPACT: [head][m][nt][lane<32] -> half4 {c0..c3}
// uint2 index = ((h*4 + m)*8 + nt)*32 + lane ; total 6144 uint2 = 24.6 KB
#define BFRAG_N (NH * 4 * 8 * 32)
__device__ __align__(16) uint2 g_bfrag[BFRAG_N];

// ---------------------------------------------------------------------------
// Kernel A (fused): weights -> smem, tiny MLP -> s_pos -> compact frag table
// ---------------------------------------------------------------------------
__device__ __forceinline__ void ln_relu_s(float* x, const float* g, const float* b, float* y) {
    float m = 0.f;
#pragma unroll
    for (int j = 0; j < POS_DIM; ++j) m += x[j];
    m *= (1.0f / POS_DIM);
    float v = 0.f;
#pragma unroll
    for (int j = 0; j < POS_DIM; ++j) { float d = x[j] - m; v += d * d; }
    v *= (1.0f / POS_DIM);
    float inv = rsqrtf(v + 1e-5f);
#pragma unroll
    for (int j = 0; j < POS_DIM; ++j) {
        float t = (x[j] - m) * inv * g[j] + b[j];
        y[j] = t > 0.f ? t : 0.f;
    }
}

__global__ void rpe_mlp_kernel(
    const float* __restrict__ w_proj, const float* __restrict__ b_proj,
    const float* __restrict__ ln1_g, const float* __restrict__ ln1_b,
    const float* __restrict__ w1, const float* __restrict__ b1,
    const float* __restrict__ ln2_g, const float* __restrict__ ln2_b,
    const float* __restrict__ w2, const float* __restrict__ b2,
    const float* __restrict__ ln3_g, const float* __restrict__ ln3_b,
    const float* __restrict__ w3, const float* __restrict__ b3)
{
    __shared__ float s_wp[2 * POS_DIM], s_bp[POS_DIM];
    __shared__ float s_g1[POS_DIM], s_c1[POS_DIM], s_w1[POS_DIM * POS_DIM], s_b1[POS_DIM];
    __shared__ float s_g2[POS_DIM], s_c2[POS_DIM], s_w2[POS_DIM * POS_DIM], s_b2[POS_DIM];
    __shared__ float s_g3[POS_DIM], s_c3[POS_DIM], s_w3[POS_DIM * NH], s_b3[NH];
    __shared__ float s_pos[NPOS * NH];

    const int tid = threadIdx.x;
    for (int i = tid; i < POS_DIM * POS_DIM; i += 256) { s_w1[i] = w1[i]; s_w2[i] = w2[i]; }
    if (tid < POS_DIM * NH) s_w3[tid] = w3[tid];
    if (tid < 2 * POS_DIM) s_wp[tid] = w_proj[tid];
    if (tid < POS_DIM) {
        s_bp[tid] = b_proj[tid];
        s_g1[tid] = ln1_g[tid]; s_c1[tid] = ln1_b[tid]; s_b1[tid] = b1[tid];
        s_g2[tid] = ln2_g[tid]; s_c2[tid] = ln2_b[tid]; s_b2[tid] = b2[tid];
        s_g3[tid] = ln3_g[tid]; s_c3[tid] = ln3_b[tid];
    }
    if (tid < NH) s_b3[tid] = b3[tid];
    __syncthreads();

    if (tid < NPOS) {
        const int m = tid;
        float in0 = (float)(m / (2 * WSZ - 1) - (HSZ - 1));
        float in1 = (float)(m % (2 * WSZ - 1) - (WSZ - 1));

        float x[POS_DIM], y[POS_DIM];
#pragma unroll
        for (int j = 0; j < POS_DIM; ++j)
            x[j] = in0 * s_wp[j] + in1 * s_wp[POS_DIM + j] + s_bp[j];

        ln_relu_s(x, s_g1, s_c1, y);
#pragma unroll
        for (int j = 0; j < POS_DIM; ++j) {
            float s = s_b1[j];
#pragma unroll
            for (int kk = 0; kk < POS_DIM; ++kk) s += y[kk] * s_w1[kk * POS_DIM + j];
            x[j] = s;
        }
        ln_relu_s(x, s_g2, s_c2, y);
#pragma unroll
        for (int j = 0; j < POS_DIM; ++j) {
            float s = s_b2[j];
#pragma unroll
            for (int kk = 0; kk < POS_DIM; ++kk) s += y[kk] * s_w2[kk * POS_DIM + j];
            x[j] = s;
        }
        ln_relu_s(x, s_g3, s_c3, y);
#pragma unroll
        for (int h = 0; h < NH; ++h) {
            float s = s_b3[h];
#pragma unroll
            for (int kk = 0; kk < POS_DIM; ++kk) s += y[kk] * s_w3[kk * NH + h];
            s_pos[m * NH + h] = s;
        }
    }
    __syncthreads();

    // phase 2: expand to compact fragment-layout fp16 table (6144 uint2)
    for (int idx = tid; idx < BFRAG_N; idx += 256) {
        int lane = idx & 31;
        int nt   = (idx >> 5) & 7;
        int m    = (idx >> 8) & 3;
        int h    = idx >> 10;
        __half hv[4];
#pragma unroll
        for (int c = 0; c < 4; ++c) {
            int r   = m * 16 + (lane >> 2) + ((c >> 1) ? 8 : 0);  // S row
            int col = nt * 8 + 2 * (lane & 3) + (c & 1);          // S col
            int dy = (r >> 3) - (col >> 3) + 7;
            int dx = (r & 7) - (col & 7) + 7;
            hv[c] = __float2half(s_pos[(dy * 15 + dx) * NH + h]);
        }
        union { __half h[4]; uint2 u; } pk;
        pk.h[0] = hv[0]; pk.h[1] = hv[1]; pk.h[2] = hv[2]; pk.h[3] = hv[3];
        g_bfrag[idx] = pk.u;
    }
}

// ---------------------------------------------------------------------------
// MMA / LDSM helpers
// ---------------------------------------------------------------------------
__device__ __forceinline__ uint32_t sh_addr(const void* p) {
    return (uint32_t)__cvta_generic_to_shared(p);
}
__device__ __forceinline__ void ldsm_x4(uint32_t& r0, uint32_t& r1, uint32_t& r2, uint32_t& r3, uint32_t a) {
    asm volatile("ldmatrix.sync.aligned.m8n8.x4.shared.b16 {%0,%1,%2,%3},[%4];"
                 : "=r"(r0), "=r"(r1), "=r"(r2), "=r"(r3) : "r"(a));
}
__device__ __forceinline__ void ldsm_x4_t(uint32_t& r0, uint32_t& r1, uint32_t& r2, uint32_t& r3, uint32_t a) {
    asm volatile("ldmatrix.sync.aligned.m8n8.x4.trans.shared.b16 {%0,%1,%2,%3},[%4];"
                 : "=r"(r0), "=r"(r1), "=r"(r2), "=r"(r3) : "r"(a));
}
__device__ __forceinline__ void mma_f16(float c[4], const uint32_t a[4], uint32_t b0, uint32_t b1) {
    asm volatile("mma.sync.aligned.m16n8k16.row.col.f32.f16.f16.f32 "
                 "{%0,%1,%2,%3},{%4,%5,%6,%7},{%8,%9},{%0,%1,%2,%3};"
                 : "+f"(c[0]), "+f"(c[1]), "+f"(c[2]), "+f"(c[3])
                 : "r"(a[0]), "r"(a[1]), "r"(a[2]), "r"(a[3]), "r"(b0), "r"(b1));
}
__device__ __forceinline__ void st_half8(__half* p, float4 f0, float4 f1) {
    union { __half2 h[4]; uint4 u; } t;
    t.h[0] = __floats2half2_rn(f0.x, f0.y);
    t.h[1] = __floats2half2_rn(f0.z, f0.w);
    t.h[2] = __floats2half2_rn(f1.x, f1.y);
    t.h[3] = __floats2half2_rn(f1.z, f1.w);
    *(uint4*)p = t.u;
}

// ---------------------------------------------------------------------------
// Kernel B: one CTA per 8x8 window. 3 iterations of 2 heads.
// 8 warps = 4 m-tiles x 2 heads; warp computes full 16x64 score rows.
// Bias: 8 coalesced L1-resident LDG.64 of compact fp16 fragments -> acc init.
// ---------------------------------------------------------------------------
__global__ __launch_bounds__(256, 4) void attn_kernel(
    const float* __restrict__ q, const float* __restrict__ k,
    const float* __restrict__ v, float* __restrict__ out)
{
    extern __shared__ __half smh[];

    const int tid = threadIdx.x;
    const int lane = tid & 31;
    const int wid = tid >> 5;
    const int t = lane & 3;        // 0..3
    const int m = wid & 3;         // m-tile
    const int hs = wid >> 2;       // head slot (0/1)

    const int w = blockIdx.x;
    const int b = w >> 10;
    const int wy = (w >> 5) & 31;
    const int wx = w & 31;

    // staging addresses: thread handles token tid>>2, channels (tid&3)*8..+8
    const int stok = tid >> 2;
    const int sch = (tid & 3) * 8;
    const int sy = wy * HSZ + (stok >> 3);
    const int sx = wx * WSZ + (stok & 7);
    const int gtok = ((b * 256 + sy) * 256 + sx) * DIM + sch;
    const int soff = stok * PADH + sch;

    // this warp's output rows
    const int r0 = m * 16 + (lane >> 2);
    const int y0 = r0 >> 3, x0 = r0 & 7;   // r1 = r0+8: one image row below
    const int obase0 = ((b * 256 + wy * HSZ + y0) * 256 + wx * WSZ + x0) * DIM;
    const int obase1 = obase0 + 256 * DIM;

    // compact bias fragment base for this (m, lane); head offset per iteration
    const uint2* bfrag_m = &g_bfrag[(m * 8) * 32 + lane];

    // LDSM lane addressing
    const int a_row = m * 16 + (lane & 7) + ((lane >> 3) & 1) * 8;
    const int a_colp = (lane >> 4) * 8;
    const int bk_row = lane & 7;
    const int bk_col = (lane >> 3) * 8;
    const int bv_tok = (lane >> 3) * 8 + (lane & 7);

#pragma unroll 1
    for (int it = 0; it < 3; ++it) {
        const int h0 = it * 2;

        // ---- stage 2 heads: Q(scaled),K,V as fp16 ----
#pragma unroll
        for (int s = 0; s < 2; ++s) {
            const int go = gtok + (h0 + s) * HEAD_DIM;
            float4 f0, f1;
            f0 = *(const float4*)(q + go);
            f1 = *(const float4*)(q + go + 4);
            f0.x *= SCALE; f0.y *= SCALE; f0.z *= SCALE; f0.w *= SCALE;
            f1.x *= SCALE; f1.y *= SCALE; f1.z *= SCALE; f1.w *= SCALE;
            st_half8(&smh[SMH_Q(s) + soff], f0, f1);
            f0 = *(const float4*)(k + go);
            f1 = *(const float4*)(k + go + 4);
            st_half8(&smh[SMH_K(s) + soff], f0, f1);
            f0 = *(const float4*)(v + go);
            f1 = *(const float4*)(v + go + 4);
            st_half8(&smh[SMH_V(s) + soff], f0, f1);
        }
        __syncthreads();

        const __half* sQ = &smh[SMH_Q(hs)];
        const __half* sK = &smh[SMH_K(hs)];
        const __half* sV = &smh[SMH_V(hs)];
        const int head = h0 + hs;

        // ---- S accumulators initialized from compact fp16 bias fragments ----
        // 8 coalesced LDG.64 (256B per warp, L1-resident: table is 24.6KB shared
        // by all CTAs on the SM), 16 transient regs.
        float sc[8][4];
        {
            const uint2* bf = bfrag_m + head * (4 * 8 * 32);
#pragma unroll
            for (int nt = 0; nt < 8; ++nt) {
                uint2 bv = bf[nt * 32];
                union { uint32_t u; __half2 h; } lo, hi;
                lo.u = bv.x; hi.u = bv.y;
                float2 f01 = __half22float2(lo.h);
                float2 f23 = __half22float2(hi.h);
                sc[nt][0] = f01.x; sc[nt][1] = f01.y;
                sc[nt][2] = f23.x; sc[nt][3] = f23.y;
            }
        }

        // ---- S += Q K^T : 16x64 per warp ----
        uint32_t aq[2][4];
#pragma unroll
        for (int kt = 0; kt < 2; ++kt)
            ldsm_x4(aq[kt][0], aq[kt][1], aq[kt][2], aq[kt][3],
                    sh_addr(&sQ[a_row * PADH + kt * 16 + a_colp]));

#pragma unroll
        for (int nt = 0; nt < 8; ++nt) {
            uint32_t b0, b1, b2, b3;
            ldsm_x4(b0, b1, b2, b3, sh_addr(&sK[(nt * 8 + bk_row) * PADH + bk_col]));
            mma_f16(sc[nt], aq[0], b0, b1);
            mma_f16(sc[nt], aq[1], b2, b3);
        }

        // ---- warp-local softmax (rows r0, r1) ----
        float mx0 = -1e30f, mx1 = -1e30f;
#pragma unroll
        for (int nt = 0; nt < 8; ++nt) {
            mx0 = fmaxf(mx0, fmaxf(sc[nt][0], sc[nt][1]));
            mx1 = fmaxf(mx1, fmaxf(sc[nt][2], sc[nt][3]));
        }
        mx0 = fmaxf(mx0, __shfl_xor_sync(0xffffffffu, mx0, 1));
        mx0 = fmaxf(mx0, __shfl_xor_sync(0xffffffffu, mx0, 2));
        mx1 = fmaxf(mx1, __shfl_xor_sync(0xffffffffu, mx1, 1));
        mx1 = fmaxf(mx1, __shfl_xor_sync(0xffffffffu, mx1, 2));

        float s0 = 0.f, s1 = 0.f;
#pragma unroll
        for (int nt = 0; nt < 8; ++nt) {
            sc[nt][0] = __expf(sc[nt][0] - mx0);
            sc[nt][1] = __expf(sc[nt][1] - mx0);
            sc[nt][2] = __expf(sc[nt][2] - mx1);
            sc[nt][3] = __expf(sc[nt][3] - mx1);
            s0 += sc[nt][0] + sc[nt][1];
            s1 += sc[nt][2] + sc[nt][3];
        }
        s0 += __shfl_xor_sync(0xffffffffu, s0, 1);
        s0 += __shfl_xor_sync(0xffffffffu, s0, 2);
        s1 += __shfl_xor_sync(0xffffffffu, s1, 1);
        s1 += __shfl_xor_sync(0xffffffffu, s1, 2);
        const float inv0 = __frcp_rn(s0);
        const float inv1 = __frcp_rn(s1);

        // ---- pack P directly into A fragments (no smem round-trip) ----
        uint32_t pa[4][4];
#pragma unroll
        for (int kt = 0; kt < 4; ++kt) {
            union { __half2 h; uint32_t u; } u0, u1, u2, u3;
            u0.h = __floats2half2_rn(sc[2 * kt][0] * inv0, sc[2 * kt][1] * inv0);
            u1.h = __floats2half2_rn(sc[2 * kt][2] * inv1, sc[2 * kt][3] * inv1);
            u2.h = __floats2half2_rn(sc[2 * kt + 1][0] * inv0, sc[2 * kt + 1][1] * inv0);
            u3.h = __floats2half2_rn(sc[2 * kt + 1][2] * inv1, sc[2 * kt + 1][3] * inv1);
            pa[kt][0] = u0.u; pa[kt][1] = u1.u; pa[kt][2] = u2.u; pa[kt][3] = u3.u;
        }

        // ---- O = P V : 16x32 per warp; per-nt accumulators (low reg pressure) ----
        const int ocol = head * HEAD_DIM + 2 * t;
#pragma unroll
        for (int nt = 0; nt < 4; ++nt) {
            float oc[4] = {0.f, 0.f, 0.f, 0.f};
#pragma unroll
            for (int hh = 0; hh < 2; ++hh) {
                uint32_t b0, b1, b2, b3;
                ldsm_x4_t(b0, b1, b2, b3,
                          sh_addr(&sV[(hh * 32 + bv_tok) * PADH + nt * 8]));
                mma_f16(oc, pa[2 * hh], b0, b1);
                mma_f16(oc, pa[2 * hh + 1], b2, b3);
            }
            *(float2*)&out[obase0 + ocol + nt * 8] = make_float2(oc[0], oc[1]);
            *(float2*)&out[obase1 + ocol + nt * 8] = make_float2(oc[2], oc[3]);
        }
        __syncthreads();   // protect smem before next iteration's stage
    }
}

// ---------------------------------------------------------------------------
extern "C" void kernel_launch(void* const* d_in, const int* in_sizes, int n_in,
                              void* d_out, int out_size)
{
    const float* q = (const float*)d_in[0];
    const float* k = (const float*)d_in[1];
    const float* v = (const float*)d_in[2];
    // d_in[3] = H, d_in[4] = W (int32, fixed 256)
    const float* w_proj = (const float*)d_in[5];
    const float* b_proj = (const float*)d_in[6];
    const float* ln1_g  = (const float*)d_in[7];
    const float* ln1_b  = (const float*)d_in[8];
    const float* w1     = (const float*)d_in[9];
    const float* b1     = (const float*)d_in[10];
    const float* ln2_g  = (const float*)d_in[11];
    const float* ln2_b  = (const float*)d_in[12];
    const float* w2     = (const float*)d_in[13];
    const float* b2     = (const float*)d_in[14];
    const float* ln3_g  = (const float*)d_in[15];
    const float* ln3_b  = (const float*)d_in[16];
    const float* w3     = (const float*)d_in[17];
    const float* b3     = (const float*)d_in[18];

    int B = in_sizes[0] / (256 * 256 * DIM);

    cudaFuncSetAttribute(attn_kernel, cudaFuncAttributeMaxDynamicSharedMemorySize, SMEM_BYTES);

    rpe_mlp_kernel<<<1, 256>>>(w_proj, b_proj, ln1_g, ln1_b, w1, b1,
                               ln2_g, ln2_b, w2, b2, ln3_g, ln3_b, w3, b3);
    attn_kernel<<<B * 1024, 256, SMEM_BYTES>>>(q, k, v, (float*)d_out);
}